// round 2
// baseline (speedup 1.0000x reference)
#include <cuda_runtime.h>

#define NN 50000
#define NE 500000
#define CC 64

// ---- persistent device scratch (no allocations allowed) ----
__device__ float g_Wsg[64 * 256];   // W_src @ W_gate
__device__ float g_Wdg[64 * 256];   // W_dst @ W_gate
__device__ float g_Wg8[8 * 256];    // W_enc @ W_gate
__device__ float g_bg[256];         // b_gate + (b_enc+b_src+b_dst) @ W_gate
__device__ float g_Gs[NN * 256];    // emb @ Wsg   (per node)
__device__ float g_Gd[NN * 256];    // emb @ Wdg   (per node)
__device__ float g_acc[NN * 256];   // [0:64]=sum s_msg, [64+i*64+c]=sum v_msg[i]

__device__ __forceinline__ void red2(float* p, float x, float y) {
    asm volatile("red.global.add.v2.f32 [%0], {%1, %2};" :: "l"(p), "f"(x), "f"(y) : "memory");
}

// ---------------------------------------------------------------------------
// 1) fold the small weight matrices
// ---------------------------------------------------------------------------
__global__ void prep_weights(const float* __restrict__ W_src, const float* __restrict__ W_dst,
                             const float* __restrict__ W_enc, const float* __restrict__ W_gate,
                             const float* __restrict__ b_gate, const float* __restrict__ b_enc,
                             const float* __restrict__ b_src, const float* __restrict__ b_dst) {
    int idx = blockIdx.x * blockDim.x + threadIdx.x;
    if (idx < 16384) {
        int k = idx >> 8, c = idx & 255;
        float s = 0.f;
        #pragma unroll 8
        for (int j = 0; j < 64; j++) s += W_src[k * 64 + j] * W_gate[j * 256 + c];
        g_Wsg[idx] = s;
    } else if (idx < 32768) {
        int t = idx - 16384;
        int k = t >> 8, c = t & 255;
        float s = 0.f;
        #pragma unroll 8
        for (int j = 0; j < 64; j++) s += W_dst[k * 64 + j] * W_gate[j * 256 + c];
        g_Wdg[t] = s;
    } else if (idx < 34816) {
        int t = idx - 32768;
        int k = t >> 8, c = t & 255;   // k < 8
        float s = 0.f;
        #pragma unroll 8
        for (int j = 0; j < 64; j++) s += W_enc[k * 64 + j] * W_gate[j * 256 + c];
        g_Wg8[t] = s;
    } else if (idx < 35072) {
        int c = idx - 34816;
        float s = b_gate[c];
        for (int j = 0; j < 64; j++) s += (b_enc[j] + b_src[j] + b_dst[j]) * W_gate[j * 256 + c];
        g_bg[c] = s;
    }
}

// ---------------------------------------------------------------------------
// 2) per-node precompute: Gs = emb @ Wsg, Gd = emb @ Wdg   (16 nodes / block)
// ---------------------------------------------------------------------------
__global__ __launch_bounds__(512) void node_pre(const float* __restrict__ emb) {
    __shared__ float es[16][64];
    int base = blockIdx.x * 16;
    for (int i = threadIdx.x; i < 16 * 64; i += 512) es[i >> 6][i & 63] = emb[base * 64 + i];
    __syncthreads();
    int t = threadIdx.x;
    int c = t & 255;
    const float* W = (t < 256) ? g_Wsg : g_Wdg;
    float* G = (t < 256) ? g_Gs : g_Gd;
    float a[16];
    #pragma unroll
    for (int n = 0; n < 16; n++) a[n] = 0.f;
    for (int k = 0; k < 64; k++) {
        float wv = W[k * 256 + c];
        #pragma unroll
        for (int n = 0; n < 16; n++) a[n] += es[n][k] * wv;
    }
    #pragma unroll
    for (int n = 0; n < 16; n++) G[(base + n) * 256 + c] = a[n];
}

// ---------------------------------------------------------------------------
// 3) zero accumulator (graph replays reuse it)
// ---------------------------------------------------------------------------
__global__ void zero_acc() {
    int i = blockIdx.x * blockDim.x + threadIdx.x;
    int stride = gridDim.x * blockDim.x;
    float4* p = (float4*)g_acc;
    const int n4 = NN * 64;
    for (; i < n4; i += stride) p[i] = make_float4(0.f, 0.f, 0.f, 0.f);
}

// ---------------------------------------------------------------------------
// 4) edge kernel: one warp per edge (grid-stride), Wg8 held in registers,
//    lane owns channels {2*lane, 2*lane+1}; scatter via red.v2 atomics.
// ---------------------------------------------------------------------------
__global__ __launch_bounds__(256) void edge_kernel(const int* __restrict__ src,
                                                   const int* __restrict__ dst,
                                                   const float* __restrict__ r_ij,
                                                   const float* __restrict__ z0g,
                                                   const float* __restrict__ z1g) {
    const int lane = threadIdx.x & 31;
    const int warp = blockIdx.x * (blockDim.x >> 5) + (threadIdx.x >> 5);
    const int nwarp = gridDim.x * (blockDim.x >> 5);

    const float2* Wg82 = (const float2*)g_Wg8;
    const float2* bg2  = (const float2*)g_bg;

    float w[4][8][2];
    float bgr[4][2];
    #pragma unroll
    for (int j = 0; j < 4; j++) {
        float2 b = bg2[j * 32 + lane];
        bgr[j][0] = b.x; bgr[j][1] = b.y;
        #pragma unroll
        for (int k = 0; k < 8; k++) {
            float2 t = Wg82[k * 128 + j * 32 + lane];
            w[j][k][0] = t.x; w[j][k][1] = t.y;
        }
    }

    const float2* Gs2 = (const float2*)g_Gs;
    const float2* Gd2 = (const float2*)g_Gd;
    const float2* z02 = (const float2*)z0g;
    const float2* z12 = (const float2*)z1g;

    for (int e = warp; e < NE; e += nwarp) {
        const int s = src[e];
        const int d = dst[e];
        const float rx = r_ij[e * 3 + 0], ry = r_ij[e * 3 + 1], rz = r_ij[e * 3 + 2];
        const float d2 = rx * rx + ry * ry + rz * rz;
        const float dd = sqrtf(d2);
        // vector_sigmoid((r*3.5)): h = 3.5 r / sqrt(1 + 12.25 |r|^2)
        const float inv = rsqrtf(1.0f + 12.25f * d2);
        const float hx = 3.5f * rx * inv, hy = 3.5f * ry * inv, hz = 3.5f * rz * inv;

        float rbf[8];
        #pragma unroll
        for (int k = 0; k < 8; k++) {
            float u = (dd - (2.0f / 7.0f) * (float)k) * 4.0f;  // sigma = 0.25
            rbf[k] = __expf(-u * u);
        }

        float g[4][2];
        #pragma unroll
        for (int j = 0; j < 4; j++) {
            float2 a = Gs2[s * 128 + j * 32 + lane];
            float2 b = Gd2[d * 128 + j * 32 + lane];
            float gx = a.x + b.x + bgr[j][0];
            float gy = a.y + b.y + bgr[j][1];
            #pragma unroll
            for (int k = 0; k < 8; k++) {
                gx += rbf[k] * w[j][k][0];
                gy += rbf[k] * w[j][k][1];
            }
            g[j][0] = gx; g[j][1] = gy;
        }

        float2 z0 = z02[d * 32 + lane];
        float2 za = z12[d * 96 + lane];
        float2 zb = z12[d * 96 + 32 + lane];
        float2 zc = z12[d * 96 + 64 + lane];

        float dotx = hx * za.x + hy * zb.x + hz * zc.x;
        float doty = hx * za.y + hy * zb.y + hz * zc.y;

        float* base = g_acc + s * 256;
        // scalar message
        red2(base + 2 * lane, g[0][0] * z0.x + g[1][0] * dotx,
                              g[0][1] * z0.y + g[1][1] * doty);
        // vector messages (i = 0,1,2)
        red2(base + 64 + 2 * lane,
             g[2][0] * za.x + g[3][0] * hx * z0.x,
             g[2][1] * za.y + g[3][1] * hx * z0.y);
        red2(base + 128 + 2 * lane,
             g[2][0] * zb.x + g[3][0] * hy * z0.x,
             g[2][1] * zb.y + g[3][1] * hy * z0.y);
        red2(base + 192 + 2 * lane,
             g[2][0] * zc.x + g[3][0] * hz * z0.x,
             g[2][1] * zc.y + g[3][1] * hz * z0.y);
    }
}

// ---------------------------------------------------------------------------
// 5) final: out0 = acc0 @ W_s ; out1[:,i,:] = accv_i @ W_v   (16 nodes/block)
// ---------------------------------------------------------------------------
__global__ __launch_bounds__(256) void final_kernel(const float* __restrict__ W_s,
                                                    const float* __restrict__ W_v,
                                                    float* __restrict__ out) {
    __shared__ float as[16][256];
    int base = blockIdx.x * 16;
    for (int i = threadIdx.x; i < 16 * 256; i += 256) as[i >> 8][i & 255] = g_acc[base * 256 + i];
    __syncthreads();
    int o = threadIdx.x;
    const float* W;
    int kb, c;
    if (o < 64) { W = W_s; kb = 0; c = o; }
    else { int i = (o - 64) >> 6; c = o & 63; W = W_v; kb = 64 + (i << 6); }
    float a[16];
    #pragma unroll
    for (int n = 0; n < 16; n++) a[n] = 0.f;
    for (int k = 0; k < 64; k++) {
        float wv = W[k * 64 + c];
        #pragma unroll
        for (int n = 0; n < 16; n++) a[n] += as[n][kb + k] * wv;
    }
    if (o < 64) {
        #pragma unroll
        for (int n = 0; n < 16; n++) out[(base + n) * 64 + c] = a[n];
    } else {
        int i = (o - 64) >> 6;
        #pragma unroll
        for (int n = 0; n < 16; n++)
            out[NN * 64 + ((base + n) * 3 + i) * 64 + c] = a[n];
    }
}

// ---------------------------------------------------------------------------
extern "C" void kernel_launch(void* const* d_in, const int* in_sizes, int n_in,
                              void* d_out, int out_size) {
    const int*   src    = (const int*)d_in[0];
    const int*   dst    = (const int*)d_in[1];
    const float* r_ij   = (const float*)d_in[2];
    const float* z_0    = (const float*)d_in[3];
    const float* z_1    = (const float*)d_in[4];
    const float* emb    = (const float*)d_in[5];
    const float* W_enc  = (const float*)d_in[6];
    const float* b_enc  = (const float*)d_in[7];
    const float* W_src  = (const float*)d_in[8];
    const float* b_src  = (const float*)d_in[9];
    const float* W_dst  = (const float*)d_in[10];
    const float* b_dst  = (const float*)d_in[11];
    // const float* W_gate = d_in[12]; used in prep
    const float* W_gate = (const float*)d_in[12];
    const float* b_gate = (const float*)d_in[13];
    const float* W_s    = (const float*)d_in[14];
    const float* W_v    = (const float*)d_in[15];
    float* out = (float*)d_out;

    prep_weights<<<137, 256>>>(W_src, W_dst, W_enc, W_gate, b_gate, b_enc, b_src, b_dst);
    node_pre<<<NN / 16, 512>>>(emb);
    zero_acc<<<2048, 256>>>();
    edge_kernel<<<888, 256>>>(src, dst, r_ij, z_0, z_1);
    final_kernel<<<NN / 16, 256>>>(W_s, W_v, out);
}

// round 3
// speedup vs baseline: 1.0598x; 1.0598x over previous
#include <cuda_runtime.h>
#include <cuda_fp16.h>

#define NN 50000
#define NE 500000

// ---- persistent device scratch ----
__device__ float  g_Wsg[64 * 256];    // W_src @ W_gate
__device__ float  g_Wdg[64 * 256];    // W_dst @ W_gate
__device__ __half g_Wg8h[8 * 256];    // W_enc @ W_gate, packed [k][j*32+l] half2 (c = j*64+2l)
__device__ float  g_bg[256];          // b_gate + (b_enc+b_src+b_dst) @ W_gate
__device__ __half g_Gs[NN * 256];     // emb @ Wsg   (fp16)
__device__ __half g_Gd[NN * 256];     // emb @ Wdg   (fp16)
__device__ __half g_z0h[NN * 64];     // z_0 fp16
__device__ __half g_z1h[NN * 192];    // z_1 fp16
__device__ float  g_acc[NN * 256];    // fp32 accumulator (s_msg | v_msg x,y,z)

__device__ __forceinline__ void red2(float* p, float x, float y) {
    asm volatile("red.global.add.v2.f32 [%0], {%1, %2};" :: "l"(p), "f"(x), "f"(y) : "memory");
}

// ---------------------------------------------------------------------------
// 1) fold small weight matrices
// ---------------------------------------------------------------------------
__global__ void prep_weights(const float* __restrict__ W_src, const float* __restrict__ W_dst,
                             const float* __restrict__ W_enc, const float* __restrict__ W_gate,
                             const float* __restrict__ b_gate, const float* __restrict__ b_enc,
                             const float* __restrict__ b_src, const float* __restrict__ b_dst) {
    int idx = blockIdx.x * blockDim.x + threadIdx.x;
    if (idx < 16384) {
        int k = idx >> 8, c = idx & 255;
        float s = 0.f;
        #pragma unroll 8
        for (int j = 0; j < 64; j++) s += W_src[k * 64 + j] * W_gate[j * 256 + c];
        g_Wsg[idx] = s;
    } else if (idx < 32768) {
        int t = idx - 16384;
        int k = t >> 8, c = t & 255;
        float s = 0.f;
        #pragma unroll 8
        for (int j = 0; j < 64; j++) s += W_dst[k * 64 + j] * W_gate[j * 256 + c];
        g_Wdg[t] = s;
    } else if (idx < 34816) {
        int t = idx - 32768;
        int k = t >> 8, c = t & 255;   // k < 8
        float s = 0.f;
        #pragma unroll 8
        for (int j = 0; j < 64; j++) s += W_enc[k * 64 + j] * W_gate[j * 256 + c];
        // pack into half2-friendly layout: element index (k*128 + j*32 + l), halves (lo,hi)
        int jj = c >> 6, within = c & 63, l = within >> 1, hi = c & 1;
        g_Wg8h[(k * 128 + jj * 32 + l) * 2 + hi] = __float2half(s);
    } else if (idx < 35072) {
        int c = idx - 34816;
        float s = b_gate[c];
        for (int j = 0; j < 64; j++) s += (b_enc[j] + b_src[j] + b_dst[j]) * W_gate[j * 256 + c];
        g_bg[c] = s;
    }
}

// ---------------------------------------------------------------------------
// 2) per-node precompute: Gs = emb @ Wsg, Gd = emb @ Wdg  (fp16 out, 16 nodes/block)
// ---------------------------------------------------------------------------
__global__ __launch_bounds__(512) void node_pre(const float* __restrict__ emb) {
    __shared__ float es[16][64];
    int base = blockIdx.x * 16;
    for (int i = threadIdx.x; i < 16 * 64; i += 512) es[i >> 6][i & 63] = emb[base * 64 + i];
    __syncthreads();
    int t = threadIdx.x;
    int c = t & 255;
    const float* W = (t < 256) ? g_Wsg : g_Wdg;
    __half* G = (t < 256) ? g_Gs : g_Gd;
    float a[16];
    #pragma unroll
    for (int n = 0; n < 16; n++) a[n] = 0.f;
    for (int k = 0; k < 64; k++) {
        float wv = W[k * 256 + c];
        #pragma unroll
        for (int n = 0; n < 16; n++) a[n] += es[n][k] * wv;
    }
    #pragma unroll
    for (int n = 0; n < 16; n++) G[(base + n) * 256 + c] = __float2half(a[n]);
}

// ---------------------------------------------------------------------------
// 3) fused: zero accumulator + convert z0/z1 to fp16
// ---------------------------------------------------------------------------
__global__ void zero_convert(const float* __restrict__ z0, const float* __restrict__ z1) {
    const int T0 = NN * 64;           // float4 count for acc zero (3.2M)
    const int T1 = T0 + NN * 32;      // half2 count for z0 (1.6M)
    const int T2 = T1 + NN * 96;      // half2 count for z1 (4.8M)
    int i = blockIdx.x * blockDim.x + threadIdx.x;
    int stride = gridDim.x * blockDim.x;
    for (; i < T2; i += stride) {
        if (i < T0) {
            ((float4*)g_acc)[i] = make_float4(0.f, 0.f, 0.f, 0.f);
        } else if (i < T1) {
            int j = i - T0;
            float2 v = ((const float2*)z0)[j];
            ((__half2*)g_z0h)[j] = __float22half2_rn(v);
        } else {
            int j = i - T1;
            float2 v = ((const float2*)z1)[j];
            ((__half2*)g_z1h)[j] = __float22half2_rn(v);
        }
    }
}

// ---------------------------------------------------------------------------
// 4) edge kernel: one warp per edge, Wg8 as half2 in regs, fp16 gathers,
//    lane owns channels {2l, 2l+1} in each of the 4 gate groups.
// ---------------------------------------------------------------------------
__global__ __launch_bounds__(256) void edge_kernel(const int* __restrict__ src,
                                                   const int* __restrict__ dst,
                                                   const float* __restrict__ r_ij) {
    const int lane = threadIdx.x & 31;
    const int warp = blockIdx.x * (blockDim.x >> 5) + (threadIdx.x >> 5);
    const int nwarp = gridDim.x * (blockDim.x >> 5);

    const __half2* Wg8h2 = (const __half2*)g_Wg8h;
    const float2*  bg2   = (const float2*)g_bg;

    __half2 w[4][8];
    float2  bgr[4];
    #pragma unroll
    for (int j = 0; j < 4; j++) {
        bgr[j] = bg2[j * 32 + lane];
        #pragma unroll
        for (int k = 0; k < 8; k++) w[j][k] = Wg8h2[k * 128 + j * 32 + lane];
    }

    const __half2* Gs2  = (const __half2*)g_Gs;
    const __half2* Gd2  = (const __half2*)g_Gd;
    const __half2* z02  = (const __half2*)g_z0h;
    const __half2* z12  = (const __half2*)g_z1h;

    for (int e = warp; e < NE; e += nwarp) {
        const int s = src[e];
        const int d = dst[e];
        const float rx = r_ij[e * 3 + 0], ry = r_ij[e * 3 + 1], rz = r_ij[e * 3 + 2];
        const float d2 = rx * rx + ry * ry + rz * rz;
        const float dd = sqrtf(d2);
        const float inv = rsqrtf(1.0f + 12.25f * d2);
        const float hx = 3.5f * rx * inv, hy = 3.5f * ry * inv, hz = 3.5f * rz * inv;

        float rbf[8];
        #pragma unroll
        for (int k = 0; k < 8; k++) {
            float u = (dd - (2.0f / 7.0f) * (float)k) * 4.0f;  // sigma = 0.25
            rbf[k] = __expf(-u * u);
        }

        // gather (fp16, L2-resident)
        __half2 hgs[4], hgd[4];
        #pragma unroll
        for (int j = 0; j < 4; j++) {
            hgs[j] = __ldg(&Gs2[s * 128 + j * 32 + lane]);
            hgd[j] = __ldg(&Gd2[d * 128 + j * 32 + lane]);
        }
        __half2 hz0 = __ldg(&z02[d * 32 + lane]);
        __half2 hza = __ldg(&z12[d * 96 + lane]);
        __half2 hzb = __ldg(&z12[d * 96 + 32 + lane]);
        __half2 hzc = __ldg(&z12[d * 96 + 64 + lane]);

        float g[4][2];
        #pragma unroll
        for (int j = 0; j < 4; j++) {
            float2 a = __half22float2(hgs[j]);
            float2 b = __half22float2(hgd[j]);
            float gx = a.x + b.x + bgr[j].x;
            float gy = a.y + b.y + bgr[j].y;
            #pragma unroll
            for (int k = 0; k < 8; k++) {
                float2 wv = __half22float2(w[j][k]);
                gx += rbf[k] * wv.x;
                gy += rbf[k] * wv.y;
            }
            g[j][0] = gx; g[j][1] = gy;
        }

        float2 z0 = __half22float2(hz0);
        float2 za = __half22float2(hza);
        float2 zb = __half22float2(hzb);
        float2 zc = __half22float2(hzc);

        float dotx = hx * za.x + hy * zb.x + hz * zc.x;
        float doty = hx * za.y + hy * zb.y + hz * zc.y;

        float* base = g_acc + s * 256;
        red2(base + 2 * lane, g[0][0] * z0.x + g[1][0] * dotx,
                              g[0][1] * z0.y + g[1][1] * doty);
        red2(base + 64 + 2 * lane,
             g[2][0] * za.x + g[3][0] * hx * z0.x,
             g[2][1] * za.y + g[3][1] * hx * z0.y);
        red2(base + 128 + 2 * lane,
             g[2][0] * zb.x + g[3][0] * hy * z0.x,
             g[2][1] * zb.y + g[3][1] * hy * z0.y);
        red2(base + 192 + 2 * lane,
             g[2][0] * zc.x + g[3][0] * hz * z0.x,
             g[2][1] * zc.y + g[3][1] * hz * z0.y);
    }
}

// ---------------------------------------------------------------------------
// 5) final: out0 = acc0 @ W_s ; out1[:,i,:] = accv_i @ W_v  (16 nodes/block)
// ---------------------------------------------------------------------------
__global__ __launch_bounds__(256) void final_kernel(const float* __restrict__ W_s,
                                                    const float* __restrict__ W_v,
                                                    float* __restrict__ out) {
    __shared__ float as[16][256];
    int base = blockIdx.x * 16;
    for (int i = threadIdx.x; i < 16 * 256; i += 256) as[i >> 8][i & 255] = g_acc[base * 256 + i];
    __syncthreads();
    int o = threadIdx.x;
    const float* W;
    int kb, c;
    if (o < 64) { W = W_s; kb = 0; c = o; }
    else { int i = (o - 64) >> 6; c = o & 63; W = W_v; kb = 64 + (i << 6); }
    float a[16];
    #pragma unroll
    for (int n = 0; n < 16; n++) a[n] = 0.f;
    for (int k = 0; k < 64; k++) {
        float wv = W[k * 64 + c];
        #pragma unroll
        for (int n = 0; n < 16; n++) a[n] += as[n][kb + k] * wv;
    }
    if (o < 64) {
        #pragma unroll
        for (int n = 0; n < 16; n++) out[(base + n) * 64 + c] = a[n];
    } else {
        int i = (o - 64) >> 6;
        #pragma unroll
        for (int n = 0; n < 16; n++)
            out[NN * 64 + ((base + n) * 3 + i) * 64 + c] = a[n];
    }
}

// ---------------------------------------------------------------------------
extern "C" void kernel_launch(void* const* d_in, const int* in_sizes, int n_in,
                              void* d_out, int out_size) {
    const int*   src    = (const int*)d_in[0];
    const int*   dst    = (const int*)d_in[1];
    const float* r_ij   = (const float*)d_in[2];
    const float* z_0    = (const float*)d_in[3];
    const float* z_1    = (const float*)d_in[4];
    const float* emb    = (const float*)d_in[5];
    const float* W_enc  = (const float*)d_in[6];
    const float* b_enc  = (const float*)d_in[7];
    const float* W_src  = (const float*)d_in[8];
    const float* b_src  = (const float*)d_in[9];
    const float* W_dst  = (const float*)d_in[10];
    const float* b_dst  = (const float*)d_in[11];
    const float* W_gate = (const float*)d_in[12];
    const float* b_gate = (const float*)d_in[13];
    const float* W_s    = (const float*)d_in[14];
    const float* W_v    = (const float*)d_in[15];
    float* out = (float*)d_out;

    zero_convert<<<2048, 256>>>(z_0, z_1);
    prep_weights<<<137, 256>>>(W_src, W_dst, W_enc, W_gate, b_gate, b_enc, b_src, b_dst);
    node_pre<<<NN / 16, 512>>>(emb);
    edge_kernel<<<888, 256>>>(src, dst, r_ij);
    final_kernel<<<NN / 16, 256>>>(W_s, W_v, out);
}